// round 16
// baseline (speedup 1.0000x reference)
#include <cuda_runtime.h>
#include <cuda_bf16.h>
#include <cuda_fp16.h>

// Problem constants
#define Bb   8
#define Nn   1024
#define Dd   512
#define Hh   8
#define DHd  64
#define MTOT (Bb*Nn)   // 8192
#define BH   (Bb*Hh)   // 64
#define LOG2E 1.4426950408889634f

// Split-bf16 operands for the Q/K projection GEMMs
__device__ __nv_bfloat16 g_xh[MTOT*Dd];
__device__ __nv_bfloat16 g_xl[MTOT*Dd];
__device__ __nv_bfloat16 g_wth[2*Dd*Dd];   // W^T per proj (Q,K): [n][k]
__device__ __nv_bfloat16 g_wtl[2*Dd*Dd];
// fp16 operands for the V projection (single-pass)
__device__ __half        g_xf[MTOT*Dd];
__device__ __half        g_wtf[Dd*Dd];     // Wv^T fp16 [n][k]

// Q/K split-bf16 head-major [BH, N, 64] (Q pre-scaled by log2e); V^T fp16 [BH, 64, N]
__device__ __nv_bfloat16 g_qh[BH*Nn*DHd];
__device__ __nv_bfloat16 g_ql[BH*Nn*DHd];
__device__ __nv_bfloat16 g_kh[BH*Nn*DHd];
__device__ __nv_bfloat16 g_kl[BH*Nn*DHd];
__device__ __half        g_vh[BH*DHd*Nn];

#define SMEM_SWZ(b) ((b) ^ (((b) >> 3) & 0x70))

static __device__ __forceinline__ unsigned smem_u32(const void* p) {
    unsigned a;
    asm("{ .reg .u64 t; cvta.to.shared.u64 t, %1; cvt.u32.u64 %0, t; }" : "=r"(a) : "l"(p));
    return a;
}

static __device__ __forceinline__ float ex2f(float x) {
    float r;
    asm("ex2.approx.f32 %0, %1;" : "=f"(r) : "f"(x));
    return r;
}

// cp.async helpers (sm_80+)
#define CP_ASYNC16(dst_u32, src_ptr) \
    asm volatile("cp.async.cg.shared.global [%0], [%1], 16;" :: "r"(dst_u32), "l"(src_ptr))
#define CP_COMMIT() asm volatile("cp.async.commit_group;")
#define CP_WAIT1()  asm volatile("cp.async.wait_group 1;")
#define CP_WAIT0()  asm volatile("cp.async.wait_group 0;")

// mma.sync m16n8k16 bf16 -> fp32
static __device__ __forceinline__ void mma16816(float* c, const unsigned* a, const unsigned* b) {
    asm volatile(
        "mma.sync.aligned.m16n8k16.row.col.f32.bf16.bf16.f32 "
        "{%0,%1,%2,%3}, {%4,%5,%6,%7}, {%8,%9}, {%0,%1,%2,%3};"
        : "+f"(c[0]), "+f"(c[1]), "+f"(c[2]), "+f"(c[3])
        : "r"(a[0]), "r"(a[1]), "r"(a[2]), "r"(a[3]), "r"(b[0]), "r"(b[1]));
}

// mma.sync m16n8k16 fp16 -> fp32
static __device__ __forceinline__ void mma16816h(float* c, const unsigned* a, const unsigned* b) {
    asm volatile(
        "mma.sync.aligned.m16n8k16.row.col.f32.f16.f16.f32 "
        "{%0,%1,%2,%3}, {%4,%5,%6,%7}, {%8,%9}, {%0,%1,%2,%3};"
        : "+f"(c[0]), "+f"(c[1]), "+f"(c[2]), "+f"(c[3])
        : "r"(a[0]), "r"(a[1]), "r"(a[2]), "r"(a[3]), "r"(b[0]), "r"(b[1]));
}

static __device__ __forceinline__ void ldsm4(unsigned* r, unsigned addr) {
    asm volatile("ldmatrix.sync.aligned.m8n8.x4.shared.b16 {%0,%1,%2,%3}, [%4];"
                 : "=r"(r[0]), "=r"(r[1]), "=r"(r[2]), "=r"(r[3]) : "r"(addr));
}

static __device__ __forceinline__ void split2(float v, __nv_bfloat16& hi, __nv_bfloat16& lo) {
    hi = __float2bfloat16(v);
    lo = __float2bfloat16(v - __bfloat162float(hi));
}

// ---------------------------------------------------------------------------
// split_x: x fp32 [8192,512] -> bf16 hi/lo + fp16. One float4 per thread.
// ---------------------------------------------------------------------------
__global__ __launch_bounds__(256) void split_x_kernel(const float* __restrict__ x)
{
    int i = blockIdx.x * 256 + threadIdx.x;          // float4 index, < 1048576
    float4 v = ((const float4*)x)[i];
    __nv_bfloat16 h[4], l[4];
    split2(v.x, h[0], l[0]); split2(v.y, h[1], l[1]);
    split2(v.z, h[2], l[2]); split2(v.w, h[3], l[3]);
    ((uint2*)g_xh)[i] = *(uint2*)h;
    ((uint2*)g_xl)[i] = *(uint2*)l;
    __half f[4];
    f[0] = __float2half(v.x); f[1] = __float2half(v.y);
    f[2] = __float2half(v.z); f[3] = __float2half(v.w);
    ((uint2*)g_xf)[i] = *(uint2*)f;
}

// ---------------------------------------------------------------------------
// split_wt: W [512,512] ([k][n]) -> W^T [n][k]. z=0,1: bf16 hi/lo; z=2: fp16.
// 64x64 tiles, grid (8, 8, 3), 256 threads.
// ---------------------------------------------------------------------------
__global__ __launch_bounds__(256) void split_wt_kernel(
    const float* __restrict__ W0, const float* __restrict__ W1,
    const float* __restrict__ W2)
{
    const int z = blockIdx.z;
    const float* W = (z == 0) ? W0 : (z == 1) ? W1 : W2;

    __shared__ unsigned short sh[64][68];
    __shared__ unsigned short sl[64][68];

    const int k0 = blockIdx.y * 64;
    const int n0 = blockIdx.x * 64;
    const int tid = threadIdx.x;

    int r = tid >> 2;
    int cs = (tid & 3) * 16;
    #pragma unroll
    for (int j = 0; j < 4; j++) {
        float4 v = *(const float4*)(W + (size_t)(k0 + r) * Dd + n0 + cs + j * 4);
        float vv[4] = {v.x, v.y, v.z, v.w};
        #pragma unroll
        for (int e = 0; e < 4; e++) {
            if (z < 2) {
                __nv_bfloat16 h, l;
                split2(vv[e], h, l);
                sh[cs + j*4 + e][r] = __bfloat16_as_ushort(h);
                sl[cs + j*4 + e][r] = __bfloat16_as_ushort(l);
            } else {
                __half f = __float2half(vv[e]);
                sh[cs + j*4 + e][r] = __half_as_ushort(f);
            }
        }
    }
    __syncthreads();

    int n = tid >> 2;
    int ks = (tid & 3) * 16;
    if (z < 2) {
        __nv_bfloat16* Oh = g_wth + (size_t)z * Dd * Dd;
        __nv_bfloat16* Ol = g_wtl + (size_t)z * Dd * Dd;
        #pragma unroll
        for (int j = 0; j < 8; j++) {
            unsigned uh = (unsigned)sh[n][ks + j*2] | ((unsigned)sh[n][ks + j*2 + 1] << 16);
            unsigned ul = (unsigned)sl[n][ks + j*2] | ((unsigned)sl[n][ks + j*2 + 1] << 16);
            *(unsigned*)(Oh + (size_t)(n0 + n) * Dd + k0 + ks + j*2) = uh;
            *(unsigned*)(Ol + (size_t)(n0 + n) * Dd + k0 + ks + j*2) = ul;
        }
    } else {
        #pragma unroll
        for (int j = 0; j < 8; j++) {
            unsigned uf = (unsigned)sh[n][ks + j*2] | ((unsigned)sh[n][ks + j*2 + 1] << 16);
            *(unsigned*)(g_wtf + (size_t)(n0 + n) * Dd + k0 + ks + j*2) = uf;
        }
    }
}

// ---------------------------------------------------------------------------
// HMMA projection GEMM, fused (gridDim.z picks proj), 2-stage cp.async pipe.
// 64x64 tile, 128 threads, KT=64 per stage, 3 CTAs/SM.
// z=0 (Q), z=1 (K): split-bf16 3-pass. z=2 (V): fp16 single-pass.
// ---------------------------------------------------------------------------
#define GOFF_AH 0
#define GOFF_AL 8192
#define GOFF_BH 16384
#define GOFF_BL 24576
#define GSTAGE  32768
#define SMEM_GEMM (2*GSTAGE)

__global__ __launch_bounds__(128, 3) void gemm_hmma_kernel(
    const float* __restrict__ bq, const float* __restrict__ bk,
    const float* __restrict__ bv)
{
    extern __shared__ char s[];
    const unsigned base_u = smem_u32(s);

    const int which = blockIdx.z;
    const float* bias = (which == 0) ? bq : (which == 1) ? bk : bv;

    const int tid  = threadIdx.x;
    const int w    = tid >> 5;        // 0..3
    const int lane = tid & 31;
    const int g    = lane >> 2;
    const int mrow = lane & 7;
    const int sel  = lane >> 3;
    const int wn0  = w * 16;          // warp n offset within 64-wide tile
    const int bm   = blockIdx.x * 64;
    const int bn   = blockIdx.y * 64;

    const int a_row_off = ((sel & 1) << 3) + mrow;
    const int a_k_off   = (sel >> 1) << 4;
    const int brow_off  = ((sel >> 1) << 3) + mrow;
    const int bkb       = (sel & 1) << 4;

    float c[4][2][4];
    #pragma unroll
    for (int mi = 0; mi < 4; mi++)
        #pragma unroll
        for (int nj = 0; nj < 2; nj++)
            #pragma unroll
            for (int v = 0; v < 4; v++) c[mi][nj][v] = 0.0f;

    if (which == 2) {
        // ---- V: fp16 single-pass ----
        const char* xf_base = (const char*)g_xf;
        const char* wf_base = (const char*)g_wtf;

        auto issueV = [&](int kt) {
            unsigned so = base_u + (kt & 1) * GSTAGE;
            unsigned ko = (unsigned)kt * 128;
            #pragma unroll
            for (int rr = 0; rr < 4; rr++) {
                int idx = tid + rr * 128;            // 0..511
                int row = idx >> 3, c16 = idx & 7;
                unsigned sw = SMEM_SWZ((unsigned)(row * 128 + c16 * 16));
                unsigned gA = (unsigned)(bm + row) * 1024 + c16 * 16 + ko;
                unsigned gB = (unsigned)(bn + row) * 1024 + c16 * 16 + ko;
                CP_ASYNC16(so + GOFF_AH + sw, xf_base + gA);
                CP_ASYNC16(so + GOFF_BH + sw, wf_base + gB);
            }
            CP_COMMIT();
        };

        issueV(0);
        for (int kt = 0; kt < 8; kt++) {
            if (kt < 7) { issueV(kt + 1); CP_WAIT1(); } else { CP_WAIT0(); }
            __syncthreads();

            unsigned sb = base_u + (kt & 1) * GSTAGE;
            #pragma unroll
            for (int ks = 0; ks < 4; ks++) {
                unsigned ah[4][4];
                #pragma unroll
                for (int mi = 0; mi < 4; mi++) {
                    unsigned sw = SMEM_SWZ((unsigned)((mi * 16 + a_row_off) * 128 + ks * 32 + a_k_off));
                    ldsm4(ah[mi], sb + GOFF_AH + sw);
                }
                unsigned bh4[4];
                {
                    unsigned sw = SMEM_SWZ((unsigned)((wn0 + brow_off) * 128 + ks * 32 + bkb));
                    ldsm4(bh4, sb + GOFF_BH + sw);
                }
                #pragma unroll
                for (int mi = 0; mi < 4; mi++)
                    #pragma unroll
                    for (int nj = 0; nj < 2; nj++)
                        mma16816h(c[mi][nj], ah[mi], bh4 + nj * 2);
            }
            __syncthreads();
        }

        // Epilogue: bias + fp16 store transposed per head
        #pragma unroll
        for (int nj = 0; nj < 2; nj++) {
            int cb = bn + wn0 + nj * 8 + (lane & 3) * 2;
            float b0 = __ldg(bias + cb), b1 = __ldg(bias + cb + 1);
            int h0 = cb >> 6, d0 = cb & 63;
            int h1 = (cb + 1) >> 6, d1 = (cb + 1) & 63;
            #pragma unroll
            for (int mi = 0; mi < 4; mi++) {
                #pragma unroll
                for (int half = 0; half < 2; half++) {
                    int m = bm + mi * 16 + g + half * 8;
                    int bb = m >> 10, ns = m & 1023;
                    float v0 = c[mi][nj][half * 2 + 0] + b0;
                    float v1 = c[mi][nj][half * 2 + 1] + b1;
                    size_t dst0 = ((size_t)(bb * Hh + h0) * DHd + d0) * Nn + ns;
                    size_t dst1 = ((size_t)(bb * Hh + h1) * DHd + d1) * Nn + ns;
                    g_vh[dst0] = __float2half(v0);
                    g_vh[dst1] = __float2half(v1);
                }
            }
        }
        return;
    }

    // ---- Q/K: split-bf16 3-pass ----
    __nv_bfloat16* Hi = (which == 0) ? g_qh : g_kh;
    __nv_bfloat16* Lo = (which == 0) ? g_ql : g_kl;
    const char* wh_base = (const char*)(g_wth + (size_t)which * Dd * Dd);
    const char* wl_base = (const char*)(g_wtl + (size_t)which * Dd * Dd);
    const char* xh_base = (const char*)g_xh;
    const char* xl_base = (const char*)g_xl;

    auto issue = [&](int kt) {
        unsigned so = base_u + (kt & 1) * GSTAGE;
        unsigned ko = (unsigned)kt * 128;
        #pragma unroll
        for (int rr = 0; rr < 4; rr++) {
            int idx = tid + rr * 128;            // 0..511
            int row = idx >> 3, c16 = idx & 7;
            unsigned sw = SMEM_SWZ((unsigned)(row * 128 + c16 * 16));
            unsigned gA = (unsigned)(bm + row) * 1024 + c16 * 16 + ko;
            unsigned gB = (unsigned)(bn + row) * 1024 + c16 * 16 + ko;
            CP_ASYNC16(so + GOFF_AH + sw, xh_base + gA);
            CP_ASYNC16(so + GOFF_AL + sw, xl_base + gA);
            CP_ASYNC16(so + GOFF_BH + sw, wh_base + gB);
            CP_ASYNC16(so + GOFF_BL + sw, wl_base + gB);
        }
        CP_COMMIT();
    };

    issue(0);
    for (int kt = 0; kt < 8; kt++) {
        if (kt < 7) { issue(kt + 1); CP_WAIT1(); } else { CP_WAIT0(); }
        __syncthreads();

        unsigned sb = base_u + (kt & 1) * GSTAGE;
        #pragma unroll
        for (int ks = 0; ks < 4; ks++) {
            unsigned ah[4][4], al[4][4];
            #pragma unroll
            for (int mi = 0; mi < 4; mi++) {
                unsigned sw = SMEM_SWZ((unsigned)((mi * 16 + a_row_off) * 128 + ks * 32 + a_k_off));
                ldsm4(ah[mi], sb + GOFF_AH + sw);
                ldsm4(al[mi], sb + GOFF_AL + sw);
            }
            unsigned bh4[4], bl4[4];
            {
                unsigned sw = SMEM_SWZ((unsigned)((wn0 + brow_off) * 128 + ks * 32 + bkb));
                ldsm4(bh4, sb + GOFF_BH + sw);
                ldsm4(bl4, sb + GOFF_BL + sw);
            }
            #pragma unroll
            for (int mi = 0; mi < 4; mi++)
                #pragma unroll
                for (int nj = 0; nj < 2; nj++) {
                    const unsigned* bp_h = bh4 + nj * 2;
                    const unsigned* bp_l = bl4 + nj * 2;
                    mma16816(c[mi][nj], ah[mi], bp_h);
                    mma16816(c[mi][nj], ah[mi], bp_l);
                    mma16816(c[mi][nj], al[mi], bp_h);
                }
        }
        __syncthreads();   // stage (kt&1) free for reuse at kt+2
    }

    // Epilogue: bias + (Q: log2e scale) + split + scatter head-major
    #pragma unroll
    for (int nj = 0; nj < 2; nj++) {
        int cb = bn + wn0 + nj * 8 + (lane & 3) * 2;
        float b0 = __ldg(bias + cb), b1 = __ldg(bias + cb + 1);
        int h0 = cb >> 6, d0 = cb & 63;
        int h1 = (cb + 1) >> 6, d1 = (cb + 1) & 63;
        #pragma unroll
        for (int mi = 0; mi < 4; mi++) {
            #pragma unroll
            for (int half = 0; half < 2; half++) {
                int m = bm + mi * 16 + g + half * 8;
                int bb = m >> 10, ns = m & 1023;
                float v0 = c[mi][nj][half * 2 + 0] + b0;
                float v1 = c[mi][nj][half * 2 + 1] + b1;
                if (which == 0) { v0 *= LOG2E; v1 *= LOG2E; }   // exp2-domain softmax
                size_t dst0 = ((size_t)(bb * Hh + h0) * Nn + ns) * DHd + d0;
                size_t dst1 = dst0 + (d1 - d0) + (size_t)(h1 - h0) * Nn * DHd;
                __nv_bfloat16 hi, lo;
                split2(v0, hi, lo); Hi[dst0] = hi; Lo[dst0] = lo;
                split2(v1, hi, lo); Hi[dst1] = hi; Lo[dst1] = lo;
            }
        }
    }
}

// ---------------------------------------------------------------------------
// HMMA flash attention, 128 threads (4 warps), 128-row q tile (32 rows/warp,
// 2 m-subtiles) to halve smem reads per MMA. 2-stage cp.async K/V pipeline.
// S: bf16 3-pass; O: fp16 single-pass; row sums via ones-column MMA.
// smem 84KB -> 2 CTAs/SM. grid = (8 q-tiles, 64 bh).
// ---------------------------------------------------------------------------
#define FOFF_Q   0
#define FOFF_QL  16384
#define FSTAGE0  32768
#define FKH 0
#define FKL 8192
#define FV  16384
#define FSTAGE   24576
#define FONES    (FSTAGE0 + 2*FSTAGE)     // 81920, 2KB ones tile
#define SMEM_FA  (FONES + 2048)           // 83968

__global__ __launch_bounds__(128, 2) void fa_kernel(float* __restrict__ y)
{
    extern __shared__ char s[];
    const unsigned base_u = smem_u32(s);

    const int tid  = threadIdx.x;
    const int w    = tid >> 5;
    const int lane = tid & 31;
    const int g    = lane >> 2;
    const int t2   = (lane & 3) * 2;
    const int bh   = blockIdx.y;
    const int b    = bh >> 3, h = bh & 7;
    const int qt   = blockIdx.x;
    const int q0   = qt * 128;
    const int wq0  = w * 32;          // warp owns 32 q rows (2 m-subtiles)

    const int mrow = lane & 7;
    const int sel  = lane >> 3;
    const int a_row_off = ((sel & 1) << 3) + mrow;
    const int a_k_off   = (sel >> 1) << 4;
    const int brow_off  = ((sel >> 1) << 3) + mrow;
    const int bkb       = (sel & 1) << 4;

    const char* kh_base = (const char*)(g_kh + (size_t)bh * Nn * DHd);
    const char* kl_base = (const char*)(g_kl + (size_t)bh * Nn * DHd);
    const char* vh_base = (const char*)(g_vh + (size_t)bh * DHd * Nn);

    // per-thread K/V load addressing (4 x 16B chunks per 8KB buffer)
    unsigned f_sw[4]; int f_row[4], f_c16[4];
    #pragma unroll
    for (int rr = 0; rr < 4; rr++) {
        int idx = tid + rr * 128;
        f_row[rr] = idx >> 3; f_c16[rr] = idx & 7;
        f_sw[rr] = SMEM_SWZ((unsigned)(f_row[rr] * 128 + f_c16[rr] * 16));
    }

    auto issue = [&](int t) {
        unsigned so = base_u + FSTAGE0 + (t & 1) * FSTAGE;
        int t0 = t << 6;
        #pragma unroll
        for (int rr = 0; rr < 4; rr++) {
            unsigned kof = (unsigned)(t0 + f_row[rr]) * 128 + f_c16[rr] * 16;
            unsigned vof = (unsigned)f_row[rr] * 2048 + (unsigned)t0 * 2 + f_c16[rr] * 16;
            CP_ASYNC16(so + FKH + f_sw[rr], kh_base + kof);
            CP_ASYNC16(so + FKL + f_sw[rr], kl_base + kof);
            CP_ASYNC16(so + FV  + f_sw[rr], vh_base + vof);
        }
        CP_COMMIT();
    };

    issue(0);   // overlap with Q load below

    // ones tile: 16 rows x 128B; row 0 = fp16 1.0, rows 1..15 = 0.
    for (int i = tid; i < 512; i += 128) {
        *(unsigned*)(s + FONES + i * 4) = (i < 32) ? 0x3C003C00u : 0u;
    }

    // Q tiles (128 q-rows x 64 d bf16, swizzled 128B rows, 16KB per split)
    const char* qh_src = (const char*)(g_qh + ((size_t)bh * Nn + q0) * DHd);
    const char* ql_src = (const char*)(g_ql + ((size_t)bh * Nn + q0) * DHd);
    #pragma unroll
    for (int rr = 0; rr < 8; rr++) {
        int idx = tid + rr * 128;         // 0..1023
        int row = idx >> 3, c16 = idx & 7;
        unsigned byte = row * 128 + c16 * 16;
        unsigned sw = SMEM_SWZ(byte);
        *(float4*)(s + FOFF_Q + sw) = *(const float4*)(qh_src + byte);
        *(float4*)(s + FOFF_QL + sw) = *(const float4*)(ql_src + byte);
    }
    __syncthreads();

    // ones B-fragment (constant across iters)
    unsigned onesb[4];
    ldsm4(onesb, base_u + FONES + SMEM_SWZ((unsigned)(brow_off * 128 + bkb)));

    float m0[2], m1[2];
    float o[2][8][4];
    float ol[2][4];               // ones-column accumulators per m-subtile
    #pragma unroll
    for (int mi = 0; mi < 2; mi++) {
        m0[mi] = -1e30f; m1[mi] = -1e30f;
        #pragma unroll
        for (int i = 0; i < 8; i++)
            #pragma unroll
            for (int v = 0; v < 4; v++) o[mi][i][v] = 0.0f;
        #pragma unroll
        for (int v = 0; v < 4; v++) ol[mi][v] = 0.0f;
    }

    for (int t = 0; t < 16; t++) {
        if (t < 15) { issue(t + 1); CP_WAIT1(); } else { CP_WAIT0(); }
        __syncthreads();

        unsigned sb = base_u + FSTAGE0 + (t & 1) * FSTAGE;

        // S = Q K^T (scores in log2 domain via Q prescale)
        float c[2][8][4];
        #pragma unroll
        for (int mi = 0; mi < 2; mi++)
            #pragma unroll
            for (int j = 0; j < 8; j++)
                #pragma unroll
                for (int v = 0; v < 4; v++) c[mi][j][v] = 0.0f;

        #pragma unroll
        for (int ks = 0; ks < 4; ks++) {
            unsigned qh4[2][4], ql4[2][4];
            #pragma unroll
            for (int mi = 0; mi < 2; mi++) {
                unsigned qsw = SMEM_SWZ((unsigned)((wq0 + mi * 16 + a_row_off) * 128 + ks * 32 + a_k_off));
                ldsm4(qh4[mi], base_u + FOFF_Q + qsw);
                ldsm4(ql4[mi], base_u + FOFF_QL + qsw);
            }
            #pragma unroll
            for (int np = 0; np < 4; np++) {
                unsigned sw = SMEM_SWZ((unsigned)((np * 16 + brow_off) * 128 + ks * 32 + bkb));
                unsigned kh4[4], kl4[4];
                ldsm4(kh4, sb + FKH + sw);
                ldsm4(kl4, sb + FKL + sw);
                #pragma unroll
                for (int mi = 0; mi < 2; mi++) {
                    mma16816(c[mi][2*np],   qh4[mi], kh4);
                    mma16816(c[mi][2*np],   qh4[mi], kl4);
                    mma16816(c[mi][2*np],   ql4[mi], kh4);
                    mma16816(c[mi][2*np+1], qh4[mi], kh4 + 2);
                    mma16816(c[mi][2*np+1], qh4[mi], kl4 + 2);
                    mma16816(c[mi][2*np+1], ql4[mi], kh4 + 2);
                }
            }
        }

        // online softmax (exp2 domain) per m-subtile
        unsigned ph[2][4][4];
        int need_rescale = 0;
        float cr0[2], cr1[2];
        #pragma unroll
        for (int mi = 0; mi < 2; mi++) {
            float rm0 = -1e30f, rm1 = -1e30f;
            #pragma unroll
            for (int j = 0; j < 8; j++) {
                rm0 = fmaxf(rm0, fmaxf(c[mi][j][0], c[mi][j][1]));
                rm1 = fmaxf(rm1, fmaxf(c[mi][j][2], c[mi][j][3]));
            }
            rm0 = fmaxf(rm0, __shfl_xor_sync(0xFFFFFFFFu, rm0, 1));
            rm0 = fmaxf(rm0, __shfl_xor_sync(0xFFFFFFFFu, rm0, 2));
            rm1 = fmaxf(rm1, __shfl_xor_sync(0xFFFFFFFFu, rm1, 1));
            rm1 = fmaxf(rm1, __shfl_xor_sync(0xFFFFFFFFu, rm1, 2));

            float mn0 = fmaxf(m0[mi], rm0), mn1 = fmaxf(m1[mi], rm1);
            cr0[mi] = ex2f(m0[mi] - mn0);
            cr1[mi] = ex2f(m1[mi] - mn1);
            m0[mi] = mn0; m1[mi] = mn1;
            need_rescale |= (cr0[mi] != 1.0f) | (cr1[mi] != 1.0f);

            #pragma unroll
            for (int j = 0; j < 8; j++) {
                c[mi][j][0] = ex2f(c[mi][j][0] - mn0);
                c[mi][j][1] = ex2f(c[mi][j][1] - mn0);
                c[mi][j][2] = ex2f(c[mi][j][2] - mn1);
                c[mi][j][3] = ex2f(c[mi][j][3] - mn1);
            }
            // P as single fp16 fragments
            #pragma unroll
            for (int ks = 0; ks < 4; ks++) {
                #pragma unroll
                for (int u = 0; u < 4; u++) {
                    int j = 2 * ks + (u >> 1);
                    int v = (u & 1) * 2;
                    __half2 hv = __floats2half2_rn(c[mi][j][v], c[mi][j][v + 1]);
                    ph[mi][ks][u] = *(unsigned*)&hv;
                }
            }
        }

        // rescale O (and l accumulators) only if any row's max moved
        if (__any_sync(0xFFFFFFFFu, need_rescale)) {
            #pragma unroll
            for (int mi = 0; mi < 2; mi++) {
                #pragma unroll
                for (int jd = 0; jd < 8; jd++) {
                    o[mi][jd][0] *= cr0[mi]; o[mi][jd][1] *= cr0[mi];
                    o[mi][jd][2] *= cr1[mi]; o[mi][jd][3] *= cr1[mi];
                }
                ol[mi][0] *= cr0[mi]; ol[mi][1] *= cr0[mi];
                ol[mi][2] *= cr1[mi]; ol[mi][3] *= cr1[mi];
            }
        }

        // O += P V (fp16), plus ones-column MMAs accumulating row sums
        #pragma unroll
        for (int ks = 0; ks < 4; ks++) {
            #pragma unroll
            for (int dp = 0; dp < 4; dp++) {
                unsigned sw = SMEM_SWZ((unsigned)((dp * 16 + brow_off) * 128 + ks * 32 + bkb));
                unsigned vh4[4];
                ldsm4(vh4, sb + FV + sw);
                #pragma unroll
                for (int mi = 0; mi < 2; mi++) {
                    mma16816h(o[mi][2*dp],   ph[mi][ks], vh4);
                    mma16816h(o[mi][2*dp+1], ph[mi][ks], vh4 + 2);
                }
            }
            #pragma unroll
            for (int mi = 0; mi < 2; mi++)
                mma16816h(ol[mi], ph[mi][ks], onesb);
        }
        __syncthreads();   // stage (t&1) reusable at t+2
    }

    // write out both m-subtiles
    #pragma unroll
    for (int mi = 0; mi < 2; mi++) {
        float lg0 = __shfl_sync(0xFFFFFFFFu, ol[mi][0], lane & 28);
        float lg1 = __shfl_sync(0xFFFFFFFFu, ol[mi][2], lane & 28);
        float inv0 = 1.0f / lg0, inv1 = 1.0f / lg1;

        int row0 = q0 + wq0 + mi * 16 + g;
        int row1 = row0 + 8;
        float* y0 = y + ((size_t)(b * Nn + row0)) * Dd + h * DHd;
        float* y1 = y + ((size_t)(b * Nn + row1)) * Dd + h * DHd;
        #pragma unroll
        for (int jd = 0; jd < 8; jd++) {
            float2 p0 = make_float2(o[mi][jd][0] * inv0, o[mi][jd][1] * inv0);
            float2 p1 = make_float2(o[mi][jd][2] * inv1, o[mi][jd][3] * inv1);
            *(float2*)(y0 + jd * 8 + t2) = p0;
            *(float2*)(y1 + jd * 8 + t2) = p1;
        }
    }
}

// ---------------------------------------------------------------------------
// Inputs (metadata order): x, Wq, bq, Wk, bk, Wv, bv. Output: float32 [B,N,D].
// ---------------------------------------------------------------------------
extern "C" void kernel_launch(void* const* d_in, const int* in_sizes, int n_in,
                              void* d_out, int out_size)
{
    const float* x  = (const float*)d_in[0];
    const float* Wq = (const float*)d_in[1];
    const float* bq = (const float*)d_in[2];
    const float* Wk = (const float*)d_in[3];
    const float* bk = (const float*)d_in[4];
    const float* Wv = (const float*)d_in[5];
    const float* bv = (const float*)d_in[6];
    float* y = (float*)d_out;

    cudaFuncSetAttribute(gemm_hmma_kernel, cudaFuncAttributeMaxDynamicSharedMemorySize, SMEM_GEMM);
    cudaFuncSetAttribute(fa_kernel, cudaFuncAttributeMaxDynamicSharedMemorySize, SMEM_FA);

    split_x_kernel<<<4096, 256>>>(x);
    split_wt_kernel<<<dim3(8, 8, 3), 256>>>(Wq, Wk, Wv);

    dim3 ggrid(MTOT / 64, Dd / 64, 3);     // (128, 8, 3) fused; z=2 is cheap V path
    gemm_hmma_kernel<<<ggrid, 128, SMEM_GEMM>>>(bq, bk, bv);

    dim3 agrid(Nn / 128, BH);              // (8, 64)
    fa_kernel<<<agrid, 128, SMEM_FA>>>(y);
}